// round 3
// baseline (speedup 1.0000x reference)
#include <cuda_runtime.h>
#include <math.h>

// Problem constants
#define VD    256          // embedding dim D
#define VD4   64           // D / 4
#define LL    32           // tokens per sequence
#define MM    4096         // mems rows
#define CC    4096         // cands rows
#define ROWS  (MM + 1)     // mems_enc rows (mems + xs)
#define NSEQ  (MM + 1 + CC)// sequences handled by encode_main (mems, ys, cands)
#define EPS   1e-8f
#define NPART 256          // partial blocks for att @ mems_enc

// Scratch (allocation-free: __device__ globals)
__device__ float g_mems_enc[ROWS * VD];   // rows 0..M-1 = encode(mems), row M = xs_emb
__device__ float g_cos[ROWS];
__device__ float g_att[ROWS];
__device__ float g_partial[NPART * VD];
__device__ float g_lhs[VD];
__device__ float g_an;                    // max(||xs_emb||, EPS)

// ---------------------------------------------------------------------------
// Block reduce helper (256 threads)
// ---------------------------------------------------------------------------
__device__ __forceinline__ float block_reduce_sum_256(float v, float* sred)
{
    const int lane = threadIdx.x & 31;
    const int wid  = threadIdx.x >> 5;
    #pragma unroll
    for (int o = 16; o; o >>= 1) v += __shfl_xor_sync(0xFFFFFFFFu, v, o);
    if (lane == 0) sred[wid] = v;
    __syncthreads();
    float r = (threadIdx.x < 8) ? sred[threadIdx.x] : 0.0f;
    if (wid == 0) {
        #pragma unroll
        for (int o = 4; o; o >>= 1) r += __shfl_xor_sync(0xFFFFFFFFu, r, o);
        if (lane == 0) sred[0] = r;
    }
    __syncthreads();
    float res = sred[0];
    __syncthreads();
    return res;
}

// ---------------------------------------------------------------------------
// Kernel 1: encode xs -> g_mems_enc row M; also its norm (g_an) and cos[M].
// 1 block x 256 threads.
// ---------------------------------------------------------------------------
__global__ void encode_xs_kernel(const int* __restrict__ xs,
                                 const float* __restrict__ lt,
                                 const float* __restrict__ freqs)
{
    __shared__ int   toks[LL];
    __shared__ float ws[LL];
    __shared__ float sred[8];

    const int t = threadIdx.x;
    if (t < LL) {
        int tok = xs[t];
        toks[t] = tok;
        float w = freqs[tok];
        float sq = w * w;
        #pragma unroll
        for (int o = 16; o; o >>= 1) sq += __shfl_xor_sync(0xFFFFFFFFu, sq, o);
        ws[t] = w * rsqrtf(sq);
    }
    __syncthreads();

    float acc = 0.0f;
    #pragma unroll
    for (int l = 0; l < LL; l++)
        acc = fmaf(ws[l], lt[(size_t)toks[l] * VD + t], acc);

    g_mems_enc[(size_t)MM * VD + t] = acc;

    float xn = block_reduce_sum_256(acc * acc, sred);
    if (t == 0) {
        float an = fmaxf(sqrtf(xn), EPS);
        g_an = an;
        g_cos[MM] = xn / (an * an);   // cos(xs, xs) per reference formula
    }
}

// ---------------------------------------------------------------------------
// Kernel 2: encode all mems / ys / cands; fused cosine-vs-xs for mems rows.
// Grid: ceil(NSEQ/4) blocks x 256 threads. Each 64-thread group = 1 sequence,
// float4 per thread (64 * 4 = 256 columns).
// ---------------------------------------------------------------------------
__global__ void encode_main_kernel(const int* __restrict__ mems,
                                   const int* __restrict__ ys,
                                   const int* __restrict__ cands,
                                   const float* __restrict__ lt,
                                   const float* __restrict__ freqs,
                                   float* __restrict__ out_ys)
{
    __shared__ int   toks[4][LL];
    __shared__ float ws[4][LL];
    __shared__ float red[4][2][2];   // [group][warp-in-group][{dot, mn}]

    const int t = threadIdx.x;
    const int g = t >> 6;            // group (sequence) within block, 0..3
    const int j = t & 63;            // float4 column index, 0..63
    const int s = blockIdx.x * 4 + g;

    const bool active = (s < NSEQ);
    const bool is_mem = active && (s < MM);

    const int* src = mems;           // safe defaults for inactive groups
    float4* dst = nullptr;
    if (active) {
        if (s < MM) {
            src = mems + (size_t)s * LL;
            dst = reinterpret_cast<float4*>(g_mems_enc) + (size_t)s * VD4;
        } else if (s == MM) {
            src = ys;
            dst = reinterpret_cast<float4*>(out_ys);            // ys -> row 0
        } else {
            const int c = s - MM - 1;
            src = cands + (size_t)c * LL;
            dst = reinterpret_cast<float4*>(out_ys) + (size_t)(1 + c) * VD4;
        }
    }

    // Warp 2g (j < 32) loads tokens + computes normalized weights
    if (active && j < LL) {
        int tok = src[j];
        toks[g][j] = tok;
        float w = freqs[tok];
        float sq = w * w;
        #pragma unroll
        for (int o = 16; o; o >>= 1) sq += __shfl_xor_sync(0xFFFFFFFFu, sq, o);
        ws[g][j] = w * rsqrtf(sq);
    }
    __syncthreads();

    float4 acc = make_float4(0.f, 0.f, 0.f, 0.f);
    if (active) {
        const float4* __restrict__ lt4 = reinterpret_cast<const float4*>(lt);
        #pragma unroll
        for (int l = 0; l < LL; l++) {
            const float w = ws[g][l];
            const float4 e = lt4[(size_t)toks[g][l] * VD4 + j];
            acc.x = fmaf(w, e.x, acc.x);
            acc.y = fmaf(w, e.y, acc.y);
            acc.z = fmaf(w, e.z, acc.z);
            acc.w = fmaf(w, e.w, acc.w);
        }
        dst[j] = acc;
    }

    // Fused cosine for mems rows: dot(row, xs_emb), ||row||^2
    if (is_mem) {
        const float4 xv = reinterpret_cast<const float4*>(g_mems_enc)[(size_t)MM * VD4 + j];
        float dot = acc.x * xv.x + acc.y * xv.y + acc.z * xv.z + acc.w * xv.w;
        float mn  = acc.x * acc.x + acc.y * acc.y + acc.z * acc.z + acc.w * acc.w;
        #pragma unroll
        for (int o = 16; o; o >>= 1) {
            dot += __shfl_xor_sync(0xFFFFFFFFu, dot, o);
            mn  += __shfl_xor_sync(0xFFFFFFFFu, mn, o);
        }
        const int wig = j >> 5;      // warp within group (0 or 1)
        if ((j & 31) == 0) { red[g][wig][0] = dot; red[g][wig][1] = mn; }
    }
    __syncthreads();

    if (is_mem && j == 0) {
        float dot = red[g][0][0] + red[g][1][0];
        float mn  = red[g][0][1] + red[g][1][1];
        float bn = fmaxf(sqrtf(mn), EPS);
        g_cos[s] = dot / (g_an * bn);
    }
}

// ---------------------------------------------------------------------------
// Kernel 3: softmax over ROWS cos values -> g_att. One block, 256 threads.
// ---------------------------------------------------------------------------
__global__ void softmax_kernel()
{
    __shared__ float sred[8];
    const int t = threadIdx.x;

    float m = -INFINITY;
    for (int r = t; r < ROWS; r += 256) m = fmaxf(m, g_cos[r]);
    {
        const int lane = t & 31, wid = t >> 5;
        #pragma unroll
        for (int o = 16; o; o >>= 1) m = fmaxf(m, __shfl_xor_sync(0xFFFFFFFFu, m, o));
        if (lane == 0) sred[wid] = m;
        __syncthreads();
        float mm = (t < 8) ? sred[t] : -INFINITY;
        if (wid == 0) {
            #pragma unroll
            for (int o = 4; o; o >>= 1) mm = fmaxf(mm, __shfl_xor_sync(0xFFFFFFFFu, mm, o));
            if (lane == 0) sred[0] = mm;
        }
        __syncthreads();
        m = sred[0];
        __syncthreads();
    }

    float s = 0.0f;
    for (int r = t; r < ROWS; r += 256) s += __expf(g_cos[r] - m);
    s = block_reduce_sum_256(s, sred);
    float inv = 1.0f / s;

    for (int r = t; r < ROWS; r += 256) g_att[r] = __expf(g_cos[r] - m) * inv;
}

// ---------------------------------------------------------------------------
// Kernel 4: partial att @ mems_enc. NPART blocks x 64 threads, float4.
// ---------------------------------------------------------------------------
__global__ void lhs_partial_kernel()
{
    const int j = threadIdx.x;   // 0..63
    const float4* __restrict__ enc4 = reinterpret_cast<const float4*>(g_mems_enc);
    float4 acc = make_float4(0.f, 0.f, 0.f, 0.f);
    for (int r = blockIdx.x; r < ROWS; r += NPART) {
        const float a = g_att[r];
        const float4 e = enc4[(size_t)r * VD4 + j];
        acc.x = fmaf(a, e.x, acc.x);
        acc.y = fmaf(a, e.y, acc.y);
        acc.z = fmaf(a, e.z, acc.z);
        acc.w = fmaf(a, e.w, acc.w);
    }
    reinterpret_cast<float4*>(g_partial)[(size_t)blockIdx.x * VD4 + j] = acc;
}

// ---------------------------------------------------------------------------
// Kernel 5: reduce partials -> g_lhs. One block, 64 threads, float4.
// ---------------------------------------------------------------------------
__global__ void lhs_final_kernel()
{
    const int j = threadIdx.x;
    const float4* __restrict__ p4 = reinterpret_cast<const float4*>(g_partial);
    float4 acc = make_float4(0.f, 0.f, 0.f, 0.f);
    #pragma unroll 8
    for (int b = 0; b < NPART; b++) {
        const float4 v = p4[(size_t)b * VD4 + j];
        acc.x += v.x; acc.y += v.y; acc.z += v.z; acc.w += v.w;
    }
    reinterpret_cast<float4*>(g_lhs)[j] = acc;
}

// ---------------------------------------------------------------------------
// Kernel 6: tile g_lhs into xs_out (C+1 identical rows). float4, 4 rows/block.
// ---------------------------------------------------------------------------
__global__ void tile_kernel(float* __restrict__ out_xs)
{
    const int t = threadIdx.x;
    const int row = blockIdx.x * 4 + (t >> 6);
    const int j = t & 63;
    if (row <= CC) {
        const float4 v = reinterpret_cast<const float4*>(g_lhs)[j];
        reinterpret_cast<float4*>(out_xs)[(size_t)row * VD4 + j] = v;
    }
}

// ---------------------------------------------------------------------------
extern "C" void kernel_launch(void* const* d_in, const int* in_sizes, int n_in,
                              void* d_out, int out_size)
{
    const int*   xs    = (const int*)  d_in[0];
    const int*   mems  = (const int*)  d_in[1];
    const int*   ys    = (const int*)  d_in[2];
    const int*   cands = (const int*)  d_in[3];
    const float* lt    = (const float*)d_in[4];
    const float* freqs = (const float*)d_in[5];

    float* out    = (float*)d_out;
    float* out_xs = out;                          // [C+1, D]
    float* out_ys = out + (size_t)(CC + 1) * VD;  // [C+1, D]

    encode_xs_kernel<<<1, VD>>>(xs, lt, freqs);
    encode_main_kernel<<<(NSEQ + 3) / 4, VD>>>(mems, ys, cands, lt, freqs, out_ys);
    softmax_kernel<<<1, VD>>>();
    lhs_partial_kernel<<<NPART, VD4>>>();
    lhs_final_kernel<<<1, VD4>>>();
    tile_kernel<<<(CC + 1 + 3) / 4, VD>>>(out_xs);
}

// round 4
// speedup vs baseline: 1.0042x; 1.0042x over previous
#include <cuda_runtime.h>
#include <math.h>

// Problem constants
#define VD    256          // embedding dim D
#define VD4   64           // D / 4
#define LL    32           // tokens per sequence
#define MM    4096         // mems rows
#define CC    4096         // cands rows
#define ROWS  (MM + 1)     // mems_enc rows (mems + xs)
#define NSEQ  (MM + 1 + CC)// sequences in main encode (mems, ys, cands)
#define EPS   1e-8f
#define NLHS  256          // blocks for att @ mems_enc partial stage

// Scratch (allocation-free: __device__ globals)
__device__ float g_mems_enc[ROWS * VD];   // rows 0..M-1 = encode(mems), row M = xs_emb
__device__ float g_cos[ROWS];
__device__ float g_att[ROWS];
__device__ float g_partial[NLHS * VD];
__device__ float g_lhs[VD];
__device__ float g_an;                    // max(||xs_emb||, EPS)

// ---------------------------------------------------------------------------
// Block reduce helper (256 threads, sum)
// ---------------------------------------------------------------------------
__device__ __forceinline__ float block_reduce_sum_256(float v, float* sred)
{
    const int lane = threadIdx.x & 31;
    const int wid  = threadIdx.x >> 5;
    #pragma unroll
    for (int o = 16; o; o >>= 1) v += __shfl_xor_sync(0xFFFFFFFFu, v, o);
    if (lane == 0) sred[wid] = v;
    __syncthreads();
    float r = (threadIdx.x < 8) ? sred[threadIdx.x] : 0.0f;
    if (wid == 0) {
        #pragma unroll
        for (int o = 4; o; o >>= 1) r += __shfl_xor_sync(0xFFFFFFFFu, r, o);
        if (lane == 0) sred[0] = r;
    }
    __syncthreads();
    float res = sred[0];
    __syncthreads();
    return res;
}

// ---------------------------------------------------------------------------
// Kernel 1: encode xs -> g_mems_enc row M; its norm (g_an) and cos[M].
// 1 block x 256 threads.
// ---------------------------------------------------------------------------
__global__ void encode_xs_kernel(const int* __restrict__ xs,
                                 const float* __restrict__ lt,
                                 const float* __restrict__ freqs)
{
    __shared__ int   toks[LL];
    __shared__ float ws[LL];
    __shared__ float sred[8];

    const int t = threadIdx.x;
    if (t < LL) {
        int tok = xs[t];
        toks[t] = tok;
        float w = freqs[tok];
        float sq = w * w;
        #pragma unroll
        for (int o = 16; o; o >>= 1) sq += __shfl_xor_sync(0xFFFFFFFFu, sq, o);
        ws[t] = w * rsqrtf(sq);
    }
    __syncthreads();

    float acc = 0.0f;
    #pragma unroll
    for (int l = 0; l < LL; l++)
        acc = fmaf(ws[l], lt[(size_t)toks[l] * VD + t], acc);

    g_mems_enc[(size_t)MM * VD + t] = acc;

    float xn = block_reduce_sum_256(acc * acc, sred);
    if (t == 0) {
        float an = fmaxf(sqrtf(xn), EPS);
        g_an = an;
        g_cos[MM] = xn / (an * an);   // cos(xs, xs) per reference formula
    }
}

// ---------------------------------------------------------------------------
// Kernel 2: scalar encode (R1-proven shape): 1 sequence per 256-thread block,
// thread t = output column t, 32 independent scalar gathers (each warp-LDG is
// exactly one 128B line of lt). Fused cosine-vs-xs for mems rows.
// Grid: NSEQ blocks.
// ---------------------------------------------------------------------------
__global__ void encode_main_kernel(const int* __restrict__ mems,
                                   const int* __restrict__ ys,
                                   const int* __restrict__ cands,
                                   const float* __restrict__ lt,
                                   const float* __restrict__ freqs,
                                   float* __restrict__ out_ys)
{
    __shared__ int   toks[LL];
    __shared__ float ws[LL];
    __shared__ float sred[8];
    __shared__ float sred2[8];

    const int s = blockIdx.x;
    const int t = threadIdx.x;
    const bool is_mem = (s < MM);

    const int* src;
    float* dst;
    if (is_mem) {                        // mems row s
        src = mems + (size_t)s * LL;
        dst = g_mems_enc + (size_t)s * VD;
    } else if (s == MM) {                // ys -> ys_out row 0
        src = ys;
        dst = out_ys;
    } else {                             // cand c -> ys_out row 1+c
        const int c = s - (MM + 1);
        src = cands + (size_t)c * LL;
        dst = out_ys + (size_t)(1 + c) * VD;
    }

    if (t < LL) {
        int tok = src[t];
        toks[t] = tok;
        float w = freqs[tok];
        float sq = w * w;
        #pragma unroll
        for (int o = 16; o; o >>= 1) sq += __shfl_xor_sync(0xFFFFFFFFu, sq, o);
        ws[t] = w * rsqrtf(sq);
    }
    __syncthreads();

    float acc = 0.0f;
    #pragma unroll
    for (int l = 0; l < LL; l++)
        acc = fmaf(ws[l], lt[(size_t)toks[l] * VD + t], acc);

    dst[t] = acc;

    // Fused cosine for mems rows: dot(row, xs_emb) and ||row||^2
    if (is_mem) {
        const float xv = g_mems_enc[(size_t)MM * VD + t];   // L2-hot, 1KB/block
        float dot = acc * xv;
        float mn  = acc * acc;
        const int lane = t & 31, wid = t >> 5;
        #pragma unroll
        for (int o = 16; o; o >>= 1) {
            dot += __shfl_xor_sync(0xFFFFFFFFu, dot, o);
            mn  += __shfl_xor_sync(0xFFFFFFFFu, mn, o);
        }
        if (lane == 0) { sred[wid] = dot; sred2[wid] = mn; }
        __syncthreads();
        if (wid == 0) {
            float d = (lane < 8) ? sred[lane]  : 0.0f;
            float m = (lane < 8) ? sred2[lane] : 0.0f;
            #pragma unroll
            for (int o = 4; o; o >>= 1) {
                d += __shfl_xor_sync(0xFFFFFFFFu, d, o);
                m += __shfl_xor_sync(0xFFFFFFFFu, m, o);
            }
            if (lane == 0) {
                float bn = fmaxf(sqrtf(m), EPS);
                g_cos[s] = d / (g_an * bn);
            }
        }
    }
}

// ---------------------------------------------------------------------------
// Kernel 3: softmax over ROWS cos values -> g_att. One block, 256 threads.
// ---------------------------------------------------------------------------
__global__ void softmax_kernel()
{
    __shared__ float sred[8];
    const int t = threadIdx.x;

    float m = -INFINITY;
    for (int r = t; r < ROWS; r += 256) m = fmaxf(m, g_cos[r]);
    {
        const int lane = t & 31, wid = t >> 5;
        #pragma unroll
        for (int o = 16; o; o >>= 1) m = fmaxf(m, __shfl_xor_sync(0xFFFFFFFFu, m, o));
        if (lane == 0) sred[wid] = m;
        __syncthreads();
        float mm = (t < 8) ? sred[t] : -INFINITY;
        if (wid == 0) {
            #pragma unroll
            for (int o = 4; o; o >>= 1) mm = fmaxf(mm, __shfl_xor_sync(0xFFFFFFFFu, mm, o));
            if (lane == 0) sred[0] = mm;
        }
        __syncthreads();
        m = sred[0];
        __syncthreads();
    }

    float s = 0.0f;
    for (int r = t; r < ROWS; r += 256) s += __expf(g_cos[r] - m);
    s = block_reduce_sum_256(s, sred);
    float inv = 1.0f / s;

    for (int r = t; r < ROWS; r += 256) g_att[r] = __expf(g_cos[r] - m) * inv;
}

// ---------------------------------------------------------------------------
// Kernel 4: partial att @ mems_enc. NLHS=256 blocks x 256 threads.
// Block b: 4 groups of 64 threads, group g handles 4 contiguous rows
// starting at (b*4+g)*4. Thread j (0..63) = float4 column. 4 independent
// float4 loads per thread -> good MLP. Block 0 / group 0 also folds row 4096.
// Groups combine via smem; block writes one 256-float partial row.
// ---------------------------------------------------------------------------
__global__ void lhs_partial_kernel()
{
    __shared__ float4 scomb[4][VD4];

    const int t = threadIdx.x;
    const int g = t >> 6;
    const int j = t & 63;
    const int base = (blockIdx.x * 4 + g) * 4;

    const float4* __restrict__ enc4 = reinterpret_cast<const float4*>(g_mems_enc);
    float4 acc = make_float4(0.f, 0.f, 0.f, 0.f);

    #pragma unroll
    for (int k = 0; k < 4; k++) {
        const int r = base + k;
        const float a = g_att[r];
        const float4 e = enc4[(size_t)r * VD4 + j];
        acc.x = fmaf(a, e.x, acc.x);
        acc.y = fmaf(a, e.y, acc.y);
        acc.z = fmaf(a, e.z, acc.z);
        acc.w = fmaf(a, e.w, acc.w);
    }
    if (blockIdx.x == 0 && g == 0) {     // extra row 4096 (xs)
        const float a = g_att[MM];
        const float4 e = enc4[(size_t)MM * VD4 + j];
        acc.x = fmaf(a, e.x, acc.x);
        acc.y = fmaf(a, e.y, acc.y);
        acc.z = fmaf(a, e.z, acc.z);
        acc.w = fmaf(a, e.w, acc.w);
    }

    scomb[g][j] = acc;
    __syncthreads();

    if (g == 0) {
        float4 a0 = scomb[0][j], a1 = scomb[1][j], a2 = scomb[2][j], a3 = scomb[3][j];
        float4 r;
        r.x = (a0.x + a1.x) + (a2.x + a3.x);
        r.y = (a0.y + a1.y) + (a2.y + a3.y);
        r.z = (a0.z + a1.z) + (a2.z + a3.z);
        r.w = (a0.w + a1.w) + (a2.w + a3.w);
        reinterpret_cast<float4*>(g_partial)[(size_t)blockIdx.x * VD4 + j] = r;
    }
}

// ---------------------------------------------------------------------------
// Kernel 5: reduce 256 partial rows -> g_lhs. One block, 256 threads, scalar
// column per thread (reads are fully coalesced across the block per row).
// ---------------------------------------------------------------------------
__global__ void lhs_final_kernel()
{
    const int t = threadIdx.x;
    float acc = 0.0f;
    #pragma unroll 8
    for (int b = 0; b < NLHS; b++)
        acc += g_partial[(size_t)b * VD + t];
    g_lhs[t] = acc;
}

// ---------------------------------------------------------------------------
// Kernel 6: tile g_lhs into xs_out (C+1 identical rows). float4, 4 rows/block.
// ---------------------------------------------------------------------------
__global__ void tile_kernel(float* __restrict__ out_xs)
{
    const int t = threadIdx.x;
    const int row = blockIdx.x * 4 + (t >> 6);
    const int j = t & 63;
    if (row <= CC) {
        const float4 v = reinterpret_cast<const float4*>(g_lhs)[j];
        reinterpret_cast<float4*>(out_xs)[(size_t)row * VD4 + j] = v;
    }
}

// ---------------------------------------------------------------------------
extern "C" void kernel_launch(void* const* d_in, const int* in_sizes, int n_in,
                              void* d_out, int out_size)
{
    const int*   xs    = (const int*)  d_in[0];
    const int*   mems  = (const int*)  d_in[1];
    const int*   ys    = (const int*)  d_in[2];
    const int*   cands = (const int*)  d_in[3];
    const float* lt    = (const float*)d_in[4];
    const float* freqs = (const float*)d_in[5];

    float* out    = (float*)d_out;
    float* out_xs = out;                          // [C+1, D]
    float* out_ys = out + (size_t)(CC + 1) * VD;  // [C+1, D]

    encode_xs_kernel<<<1, VD>>>(xs, lt, freqs);
    encode_main_kernel<<<NSEQ, VD>>>(mems, ys, cands, lt, freqs, out_ys);
    softmax_kernel<<<1, VD>>>();
    lhs_partial_kernel<<<NLHS, VD>>>();
    lhs_final_kernel<<<1, VD>>>();
    tile_kernel<<<(CC + 1 + 3) / 4, VD>>>(out_xs);
}

// round 5
// speedup vs baseline: 1.2775x; 1.2722x over previous
#include <cuda_runtime.h>
#include <math.h>

// Problem constants
#define VD    256          // embedding dim D
#define VD4   64           // D / 4
#define LL    32           // tokens per sequence
#define MM    4096         // mems rows
#define CC    4096         // cands rows
#define ROWS  (MM + 1)     // mems_enc rows (mems + xs)
#define NSEQ  (MM + 2 + CC)// all sequences: mems, xs, ys, cands
#define EPS   1e-8f
#define NLHS  256          // blocks for att @ mems_enc partial stage

// Scratch (allocation-free: __device__ globals)
__device__ float g_mems_enc[ROWS * VD];   // rows 0..M-1 = encode(mems), row M = xs_emb
__device__ float g_cos[ROWS];
__device__ float g_att[ROWS];
__device__ float g_partial[NLHS * VD];
__device__ float g_lhs[VD];

// ---------------------------------------------------------------------------
// Block reduce helper (256 threads, sum)
// ---------------------------------------------------------------------------
__device__ __forceinline__ float block_reduce_sum_256(float v, float* sred)
{
    const int lane = threadIdx.x & 31;
    const int wid  = threadIdx.x >> 5;
    #pragma unroll
    for (int o = 16; o; o >>= 1) v += __shfl_xor_sync(0xFFFFFFFFu, v, o);
    if (lane == 0) sred[wid] = v;
    __syncthreads();
    float r = (threadIdx.x < 8) ? sred[threadIdx.x] : 0.0f;
    if (wid == 0) {
        #pragma unroll
        for (int o = 4; o; o >>= 1) r += __shfl_xor_sync(0xFFFFFFFFu, r, o);
        if (lane == 0) sred[0] = r;
    }
    __syncthreads();
    float res = sred[0];
    __syncthreads();
    return res;
}

// ---------------------------------------------------------------------------
// Kernel 1: encode ALL sequences (mems, xs, ys, cands) — one launch.
// ceil(NSEQ/4) blocks x 256 threads; each 64-thread group = 1 sequence,
// thread j (0..63) owns one float4 column. No fusion, no tail reduction.
// ---------------------------------------------------------------------------
__global__ void encode_kernel(const int* __restrict__ xs,
                              const int* __restrict__ mems,
                              const int* __restrict__ ys,
                              const int* __restrict__ cands,
                              const float* __restrict__ lt,
                              const float* __restrict__ freqs,
                              float* __restrict__ out_ys)
{
    __shared__ int   toks[4][LL];
    __shared__ float ws[4][LL];

    const int t = threadIdx.x;
    const int g = t >> 6;            // group (sequence) within block, 0..3
    const int j = t & 63;            // float4 column index, 0..63
    const int s = blockIdx.x * 4 + g;

    const bool active = (s < NSEQ);

    const int* src = mems;
    float4* dst = nullptr;
    if (active) {
        if (s < MM) {                             // mems row s
            src = mems + (size_t)s * LL;
            dst = reinterpret_cast<float4*>(g_mems_enc) + (size_t)s * VD4;
        } else if (s == MM) {                     // xs -> mems_enc row M
            src = xs;
            dst = reinterpret_cast<float4*>(g_mems_enc) + (size_t)MM * VD4;
        } else if (s == MM + 1) {                 // ys -> ys_out row 0
            src = ys;
            dst = reinterpret_cast<float4*>(out_ys);
        } else {                                  // cand c -> ys_out row 1+c
            const int c = s - (MM + 2);
            src = cands + (size_t)c * LL;
            dst = reinterpret_cast<float4*>(out_ys) + (size_t)(1 + c) * VD4;
        }
    }

    // First warp of each group loads tokens + computes normalized weights
    if (active && j < LL) {
        int tok = src[j];
        toks[g][j] = tok;
        float w = freqs[tok];
        float sq = w * w;
        #pragma unroll
        for (int o = 16; o; o >>= 1) sq += __shfl_xor_sync(0xFFFFFFFFu, sq, o);
        ws[g][j] = w * rsqrtf(sq);
    }
    __syncthreads();

    if (active) {
        const float4* __restrict__ lt4 = reinterpret_cast<const float4*>(lt);
        float4 acc = make_float4(0.f, 0.f, 0.f, 0.f);
        #pragma unroll
        for (int l = 0; l < LL; l++) {
            const float w = ws[g][l];
            const float4 e = lt4[(size_t)toks[g][l] * VD4 + j];
            acc.x = fmaf(w, e.x, acc.x);
            acc.y = fmaf(w, e.y, acc.y);
            acc.z = fmaf(w, e.z, acc.z);
            acc.w = fmaf(w, e.w, acc.w);
        }
        dst[j] = acc;
    }
}

// ---------------------------------------------------------------------------
// Kernel 2: cosine of every mems_enc row vs row M (xs). 4 rows per block,
// 64 threads per row, float4, single shuffle pass carrying {dot, mn, xn}.
// Grid: ceil(ROWS/4) blocks x 256.
// ---------------------------------------------------------------------------
__global__ void cos_kernel()
{
    __shared__ float red[4][2][3];   // [group][warp-in-group][{dot, mn, xn}]

    const int t = threadIdx.x;
    const int g = t >> 6;
    const int j = t & 63;
    const int r = blockIdx.x * 4 + g;
    if (r >= ROWS) return;

    const float4* __restrict__ enc4 = reinterpret_cast<const float4*>(g_mems_enc);
    const float4 mv = enc4[(size_t)r  * VD4 + j];
    const float4 xv = enc4[(size_t)MM * VD4 + j];

    float dot = mv.x * xv.x + mv.y * xv.y + mv.z * xv.z + mv.w * xv.w;
    float mn  = mv.x * mv.x + mv.y * mv.y + mv.z * mv.z + mv.w * mv.w;
    float xn  = xv.x * xv.x + xv.y * xv.y + xv.z * xv.z + xv.w * xv.w;

    #pragma unroll
    for (int o = 16; o; o >>= 1) {
        dot += __shfl_xor_sync(0xFFFFFFFFu, dot, o);
        mn  += __shfl_xor_sync(0xFFFFFFFFu, mn, o);
        xn  += __shfl_xor_sync(0xFFFFFFFFu, xn, o);
    }
    const int wig = j >> 5;
    if ((j & 31) == 0) {
        red[g][wig][0] = dot; red[g][wig][1] = mn; red[g][wig][2] = xn;
    }
    __syncthreads();

    if (j == 0) {
        float d  = red[g][0][0] + red[g][1][0];
        float m  = red[g][0][1] + red[g][1][1];
        float x2 = red[g][0][2] + red[g][1][2];
        float an = fmaxf(sqrtf(x2), EPS);
        float bn = fmaxf(sqrtf(m),  EPS);
        g_cos[r] = d / (an * bn);
    }
}

// ---------------------------------------------------------------------------
// Kernel 3: softmax over ROWS cos values -> g_att. One block, 256 threads.
// ---------------------------------------------------------------------------
__global__ void softmax_kernel()
{
    __shared__ float sred[8];
    const int t = threadIdx.x;

    float m = -INFINITY;
    for (int r = t; r < ROWS; r += 256) m = fmaxf(m, g_cos[r]);
    {
        const int lane = t & 31, wid = t >> 5;
        #pragma unroll
        for (int o = 16; o; o >>= 1) m = fmaxf(m, __shfl_xor_sync(0xFFFFFFFFu, m, o));
        if (lane == 0) sred[wid] = m;
        __syncthreads();
        float mm = (t < 8) ? sred[t] : -INFINITY;
        if (wid == 0) {
            #pragma unroll
            for (int o = 4; o; o >>= 1) mm = fmaxf(mm, __shfl_xor_sync(0xFFFFFFFFu, mm, o));
            if (lane == 0) sred[0] = mm;
        }
        __syncthreads();
        m = sred[0];
        __syncthreads();
    }

    float s = 0.0f;
    for (int r = t; r < ROWS; r += 256) s += __expf(g_cos[r] - m);
    s = block_reduce_sum_256(s, sred);
    float inv = 1.0f / s;

    for (int r = t; r < ROWS; r += 256) g_att[r] = __expf(g_cos[r] - m) * inv;
}

// ---------------------------------------------------------------------------
// Kernel 4: partial att @ mems_enc. 256 blocks x 256 threads; each 64-thread
// group handles 4 contiguous rows (float4 cols) -> 4-deep MLP; block combine.
// Block 0 / group 0 also folds row 4096 (xs).
// ---------------------------------------------------------------------------
__global__ void lhs_partial_kernel()
{
    __shared__ float4 scomb[4][VD4];

    const int t = threadIdx.x;
    const int g = t >> 6;
    const int j = t & 63;
    const int base = (blockIdx.x * 4 + g) * 4;

    const float4* __restrict__ enc4 = reinterpret_cast<const float4*>(g_mems_enc);
    float4 acc = make_float4(0.f, 0.f, 0.f, 0.f);

    #pragma unroll
    for (int k = 0; k < 4; k++) {
        const int r = base + k;
        const float a = g_att[r];
        const float4 e = enc4[(size_t)r * VD4 + j];
        acc.x = fmaf(a, e.x, acc.x);
        acc.y = fmaf(a, e.y, acc.y);
        acc.z = fmaf(a, e.z, acc.z);
        acc.w = fmaf(a, e.w, acc.w);
    }
    if (blockIdx.x == 0 && g == 0) {     // extra row 4096 (xs)
        const float a = g_att[MM];
        const float4 e = enc4[(size_t)MM * VD4 + j];
        acc.x = fmaf(a, e.x, acc.x);
        acc.y = fmaf(a, e.y, acc.y);
        acc.z = fmaf(a, e.z, acc.z);
        acc.w = fmaf(a, e.w, acc.w);
    }

    scomb[g][j] = acc;
    __syncthreads();

    if (g == 0) {
        float4 a0 = scomb[0][j], a1 = scomb[1][j], a2 = scomb[2][j], a3 = scomb[3][j];
        float4 r;
        r.x = (a0.x + a1.x) + (a2.x + a3.x);
        r.y = (a0.y + a1.y) + (a2.y + a3.y);
        r.z = (a0.z + a1.z) + (a2.z + a3.z);
        r.w = (a0.w + a1.w) + (a2.w + a3.w);
        reinterpret_cast<float4*>(g_partial)[(size_t)blockIdx.x * VD4 + j] = r;
    }
}

// ---------------------------------------------------------------------------
// Kernel 5: reduce 256 partial rows -> g_lhs. One block, 256 threads.
// ---------------------------------------------------------------------------
__global__ void lhs_final_kernel()
{
    const int t = threadIdx.x;
    float acc = 0.0f;
    #pragma unroll 8
    for (int b = 0; b < NLHS; b++)
        acc += g_partial[(size_t)b * VD + t];
    g_lhs[t] = acc;
}

// ---------------------------------------------------------------------------
// Kernel 6: tile g_lhs into xs_out (C+1 identical rows). float4, 4 rows/block.
// ---------------------------------------------------------------------------
__global__ void tile_kernel(float* __restrict__ out_xs)
{
    const int t = threadIdx.x;
    const int row = blockIdx.x * 4 + (t >> 6);
    const int j = t & 63;
    if (row <= CC) {
        const float4 v = reinterpret_cast<const float4*>(g_lhs)[j];
        reinterpret_cast<float4*>(out_xs)[(size_t)row * VD4 + j] = v;
    }
}

// ---------------------------------------------------------------------------
extern "C" void kernel_launch(void* const* d_in, const int* in_sizes, int n_in,
                              void* d_out, int out_size)
{
    const int*   xs    = (const int*)  d_in[0];
    const int*   mems  = (const int*)  d_in[1];
    const int*   ys    = (const int*)  d_in[2];
    const int*   cands = (const int*)  d_in[3];
    const float* lt    = (const float*)d_in[4];
    const float* freqs = (const float*)d_in[5];

    float* out    = (float*)d_out;
    float* out_xs = out;                          // [C+1, D]
    float* out_ys = out + (size_t)(CC + 1) * VD;  // [C+1, D]

    encode_kernel<<<(NSEQ + 3) / 4, VD>>>(xs, mems, ys, cands, lt, freqs, out_ys);
    cos_kernel<<<(ROWS + 3) / 4, VD>>>();
    softmax_kernel<<<1, VD>>>();
    lhs_partial_kernel<<<NLHS, VD>>>();
    lhs_final_kernel<<<1, VD>>>();
    tile_kernel<<<(CC + 1 + 3) / 4, VD>>>(out_xs);
}

// round 7
// speedup vs baseline: 1.5032x; 1.1766x over previous
#include <cuda_runtime.h>
#include <math.h>

// Problem constants
#define VD    256          // embedding dim D
#define VD4   64           // D / 4
#define LL    32           // tokens per sequence
#define MM    4096         // mems rows
#define CC    4096         // cands rows
#define ROWS  (MM + 1)     // mems_enc rows (mems + xs)
#define NSEQ  (MM + 2 + CC)// all sequences: mems, xs, ys, cands
#define EPS   1e-8f
#define NLHS  256          // blocks for att @ mems_enc partial stage

// Scratch (allocation-free: __device__ globals)
__device__ float g_mems_enc[ROWS * VD];   // rows 0..M-1 = encode(mems), row M = xs_emb
__device__ float g_cos[ROWS];
__device__ float g_partial[NLHS * VD];
__device__ float g_lhs[VD];

// ---------------------------------------------------------------------------
// Kernel 1: encode ALL sequences (mems, xs, ys, cands) — one launch.
// ceil(NSEQ/4) blocks x 256 threads; each 64-thread group = 1 sequence,
// thread j (0..63) owns one float4 column. Stores are streaming (__stcs) so
// they don't evict lt from L2.
// ---------------------------------------------------------------------------
__global__ void encode_kernel(const int* __restrict__ xs,
                              const int* __restrict__ mems,
                              const int* __restrict__ ys,
                              const int* __restrict__ cands,
                              const float* __restrict__ lt,
                              const float* __restrict__ freqs,
                              float* __restrict__ out_ys)
{
    __shared__ int   toks[4][LL];
    __shared__ float ws[4][LL];

    const int t = threadIdx.x;
    const int g = t >> 6;            // group (sequence) within block, 0..3
    const int j = t & 63;            // float4 column index, 0..63
    const int s = blockIdx.x * 4 + g;

    const bool active = (s < NSEQ);

    const int* src = mems;
    float4* dst = nullptr;
    if (active) {
        if (s < MM) {                             // mems row s
            src = mems + (size_t)s * LL;
            dst = reinterpret_cast<float4*>(g_mems_enc) + (size_t)s * VD4;
        } else if (s == MM) {                     // xs -> mems_enc row M
            src = xs;
            dst = reinterpret_cast<float4*>(g_mems_enc) + (size_t)MM * VD4;
        } else if (s == MM + 1) {                 // ys -> ys_out row 0
            src = ys;
            dst = reinterpret_cast<float4*>(out_ys);
        } else {                                  // cand c -> ys_out row 1+c
            const int c = s - (MM + 2);
            src = cands + (size_t)c * LL;
            dst = reinterpret_cast<float4*>(out_ys) + (size_t)(1 + c) * VD4;
        }
    }

    // First warp of each group loads tokens + computes normalized weights
    if (active && j < LL) {
        int tok = src[j];
        toks[g][j] = tok;
        float w = freqs[tok];
        float sq = w * w;
        #pragma unroll
        for (int o = 16; o; o >>= 1) sq += __shfl_xor_sync(0xFFFFFFFFu, sq, o);
        ws[g][j] = w * rsqrtf(sq);
    }
    __syncthreads();

    if (active) {
        const float4* __restrict__ lt4 = reinterpret_cast<const float4*>(lt);
        float4 acc = make_float4(0.f, 0.f, 0.f, 0.f);
        #pragma unroll
        for (int l = 0; l < LL; l++) {
            const float w = ws[g][l];
            const float4 e = lt4[(size_t)toks[g][l] * VD4 + j];
            acc.x = fmaf(w, e.x, acc.x);
            acc.y = fmaf(w, e.y, acc.y);
            acc.z = fmaf(w, e.z, acc.z);
            acc.w = fmaf(w, e.w, acc.w);
        }
        __stcs(dst + j, acc);        // streaming store: keep lt resident
    }
}

// ---------------------------------------------------------------------------
// Kernel 2: cosine of every mems_enc row vs row M (xs). 4 rows per block,
// 64 threads per row, float4. Row reads use __ldcs (single-pass streaming);
// xs row read normally (hot, reused by every block).
// ---------------------------------------------------------------------------
__global__ void cos_kernel()
{
    __shared__ float red[4][2][3];   // [group][warp-in-group][{dot, mn, xn}]

    const int t = threadIdx.x;
    const int g = t >> 6;
    const int j = t & 63;
    const int r = blockIdx.x * 4 + g;
    if (r >= ROWS) return;

    const float4* __restrict__ enc4 = reinterpret_cast<const float4*>(g_mems_enc);
    const float4 mv = __ldcs(enc4 + (size_t)r * VD4 + j);
    const float4 xv = enc4[(size_t)MM * VD4 + j];

    float dot = mv.x * xv.x + mv.y * xv.y + mv.z * xv.z + mv.w * xv.w;
    float mn  = mv.x * mv.x + mv.y * mv.y + mv.z * mv.z + mv.w * mv.w;
    float xn  = xv.x * xv.x + xv.y * xv.y + xv.z * xv.z + xv.w * xv.w;

    #pragma unroll
    for (int o = 16; o; o >>= 1) {
        dot += __shfl_xor_sync(0xFFFFFFFFu, dot, o);
        mn  += __shfl_xor_sync(0xFFFFFFFFu, mn, o);
        xn  += __shfl_xor_sync(0xFFFFFFFFu, xn, o);
    }
    const int wig = j >> 5;
    if ((j & 31) == 0) {
        red[g][wig][0] = dot; red[g][wig][1] = mn; red[g][wig][2] = xn;
    }
    __syncthreads();

    if (j == 0) {
        float d  = red[g][0][0] + red[g][1][0];
        float m  = red[g][0][1] + red[g][1][1];
        float x2 = red[g][0][2] + red[g][1][2];
        float an = fmaxf(sqrtf(x2), EPS);
        float bn = fmaxf(sqrtf(m),  EPS);
        g_cos[r] = d / (an * bn);
    }
}

// ---------------------------------------------------------------------------
// Kernel 3: fused softmax + partial att @ mems_enc.
// 256 blocks x 256 threads. Each block FIRST recomputes the softmax stats
// (max, sum) from g_cos redundantly (16KB, L2-hot), then computes its
// partial weighted row sum. Deterministic: same data, same per-block order.
// Block 0 / group 0 also folds row 4096 (xs).
// ---------------------------------------------------------------------------
__global__ void lhs_partial_kernel()
{
    __shared__ float  sred[8];
    __shared__ float4 scomb[4][VD4];

    const int t = threadIdx.x;
    const int lane = t & 31;
    const int wid  = t >> 5;

    // --- softmax stats over g_cos ---
    float m = -INFINITY;
    for (int r = t; r < ROWS; r += 256) m = fmaxf(m, g_cos[r]);
    #pragma unroll
    for (int o = 16; o; o >>= 1) m = fmaxf(m, __shfl_xor_sync(0xFFFFFFFFu, m, o));
    if (lane == 0) sred[wid] = m;
    __syncthreads();
    {
        float mm = (t < 8) ? sred[t] : -INFINITY;
        if (wid == 0) {
            #pragma unroll
            for (int o = 4; o; o >>= 1) mm = fmaxf(mm, __shfl_xor_sync(0xFFFFFFFFu, mm, o));
            if (lane == 0) sred[0] = mm;
        }
    }
    __syncthreads();
    m = sred[0];
    __syncthreads();

    float s = 0.0f;
    for (int r = t; r < ROWS; r += 256) s += __expf(g_cos[r] - m);
    #pragma unroll
    for (int o = 16; o; o >>= 1) s += __shfl_xor_sync(0xFFFFFFFFu, s, o);
    if (lane == 0) sred[wid] = s;
    __syncthreads();
    {
        float ss = (t < 8) ? sred[t] : 0.0f;
        if (wid == 0) {
            #pragma unroll
            for (int o = 4; o; o >>= 1) ss += __shfl_xor_sync(0xFFFFFFFFu, ss, o);
            if (lane == 0) sred[0] = ss;
        }
    }
    __syncthreads();
    const float inv = 1.0f / sred[0];

    // --- partial weighted sum ---
    const int g = t >> 6;
    const int j = t & 63;
    const int base = (blockIdx.x * 4 + g) * 4;

    const float4* __restrict__ enc4 = reinterpret_cast<const float4*>(g_mems_enc);
    float4 acc = make_float4(0.f, 0.f, 0.f, 0.f);

    #pragma unroll
    for (int k = 0; k < 4; k++) {
        const int r = base + k;
        const float a = __expf(g_cos[r] - m) * inv;
        const float4 e = __ldcs(enc4 + (size_t)r * VD4 + j);
        acc.x = fmaf(a, e.x, acc.x);
        acc.y = fmaf(a, e.y, acc.y);
        acc.z = fmaf(a, e.z, acc.z);
        acc.w = fmaf(a, e.w, acc.w);
    }
    if (blockIdx.x == 0 && g == 0) {     // extra row 4096 (xs)
        const float a = __expf(g_cos[MM] - m) * inv;
        const float4 e = enc4[(size_t)MM * VD4 + j];
        acc.x = fmaf(a, e.x, acc.x);
        acc.y = fmaf(a, e.y, acc.y);
        acc.z = fmaf(a, e.z, acc.z);
        acc.w = fmaf(a, e.w, acc.w);
    }

    scomb[g][j] = acc;
    __syncthreads();

    if (g == 0) {
        float4 a0 = scomb[0][j], a1 = scomb[1][j], a2 = scomb[2][j], a3 = scomb[3][j];
        float4 r;
        r.x = (a0.x + a1.x) + (a2.x + a3.x);
        r.y = (a0.y + a1.y) + (a2.y + a3.y);
        r.z = (a0.z + a1.z) + (a2.z + a3.z);
        r.w = (a0.w + a1.w) + (a2.w + a3.w);
        __stcs(reinterpret_cast<float4*>(g_partial) + (size_t)blockIdx.x * VD4 + j, r);
    }
}

// ---------------------------------------------------------------------------
// Kernel 4: reduce 256 partial rows -> g_lhs. One block, 256 threads.
// Thread t: float4 column j = t&63, row chunk (t>>6)*64..+63; smem combine.
// ---------------------------------------------------------------------------
__global__ void lhs_final_kernel()
{
    __shared__ float4 scomb[4][VD4];

    const int t = threadIdx.x;
    const int g = t >> 6;
    const int j = t & 63;

    const float4* __restrict__ p4 = reinterpret_cast<const float4*>(g_partial);
    float4 acc = make_float4(0.f, 0.f, 0.f, 0.f);
    #pragma unroll 8
    for (int b = g * 64; b < (g + 1) * 64; b++) {
        const float4 v = __ldcs(p4 + (size_t)b * VD4 + j);
        acc.x += v.x; acc.y += v.y; acc.z += v.z; acc.w += v.w;
    }
    scomb[g][j] = acc;
    __syncthreads();

    if (g == 0) {
        float4 a0 = scomb[0][j], a1 = scomb[1][j], a2 = scomb[2][j], a3 = scomb[3][j];
        float4 r;
        r.x = (a0.x + a1.x) + (a2.x + a3.x);
        r.y = (a0.y + a1.y) + (a2.y + a3.y);
        r.z = (a0.z + a1.z) + (a2.z + a3.z);
        r.w = (a0.w + a1.w) + (a2.w + a3.w);
        reinterpret_cast<float4*>(g_lhs)[j] = r;
    }
}

// ---------------------------------------------------------------------------
// Kernel 5: tile g_lhs into xs_out (C+1 identical rows). float4, 4 rows/block,
// streaming stores.
// ---------------------------------------------------------------------------
__global__ void tile_kernel(float* __restrict__ out_xs)
{
    const int t = threadIdx.x;
    const int row = blockIdx.x * 4 + (t >> 6);
    const int j = t & 63;
    if (row <= CC) {
        const float4 v = reinterpret_cast<const float4*>(g_lhs)[j];
        __stcs(reinterpret_cast<float4*>(out_xs) + (size_t)row * VD4 + j, v);
    }
}

// ---------------------------------------------------------------------------
extern "C" void kernel_launch(void* const* d_in, const int* in_sizes, int n_in,
                              void* d_out, int out_size)
{
    const int*   xs    = (const int*)  d_in[0];
    const int*   mems  = (const int*)  d_in[1];
    const int*   ys    = (const int*)  d_in[2];
    const int*   cands = (const int*)  d_in[3];
    const float* lt    = (const float*)d_in[4];
    const float* freqs = (const float*)d_in[5];

    float* out    = (float*)d_out;
    float* out_xs = out;                          // [C+1, D]
    float* out_ys = out + (size_t)(CC + 1) * VD;  // [C+1, D]

    encode_kernel<<<(NSEQ + 3) / 4, VD>>>(xs, mems, ys, cands, lt, freqs, out_ys);
    cos_kernel<<<(ROWS + 3) / 4, VD>>>();
    lhs_partial_kernel<<<NLHS, VD>>>();
    lhs_final_kernel<<<1, VD>>>();
    tile_kernel<<<(CC + 1 + 3) / 4, VD>>>(out_xs);
}

// round 8
// speedup vs baseline: 1.5703x; 1.0447x over previous
#include <cuda_runtime.h>
#include <math.h>

// Problem constants
#define VD    256          // embedding dim D
#define VD4   64           // D / 4
#define LL    32           // tokens per sequence
#define MM    4096         // mems rows
#define CC    4096         // cands rows
#define ROWS  (MM + 1)     // mems_enc rows (mems + xs)
#define NSEQ  (MM + 2 + CC)// all sequences: mems, xs, ys, cands
#define EPS   1e-8f
#define NLHS  256          // blocks for att @ mems_enc partial stage

// Scratch (allocation-free: __device__ globals)
__device__ float g_mems_enc[ROWS * VD];   // rows 0..M-1 = encode(mems), row M = xs_emb
__device__ float g_cos[ROWS];
__device__ float g_partial[NLHS * VD];
__device__ float g_lhs[VD];

// ---------------------------------------------------------------------------
// Kernel 1: encode ALL sequences (mems, xs, ys, cands) — one launch.
// ceil(NSEQ/4) blocks x 256 threads; each 64-thread group = 1 sequence,
// thread j (0..63) owns one float4 column. Stores are streaming (__stcs) so
// they don't evict lt from L2.
// ---------------------------------------------------------------------------
__global__ void encode_kernel(const int* __restrict__ xs,
                              const int* __restrict__ mems,
                              const int* __restrict__ ys,
                              const int* __restrict__ cands,
                              const float* __restrict__ lt,
                              const float* __restrict__ freqs,
                              float* __restrict__ out_ys)
{
    __shared__ int   toks[4][LL];
    __shared__ float ws[4][LL];

    const int t = threadIdx.x;
    const int g = t >> 6;            // group (sequence) within block, 0..3
    const int j = t & 63;            // float4 column index, 0..63
    const int s = blockIdx.x * 4 + g;

    const bool active = (s < NSEQ);

    const int* src = mems;
    float4* dst = nullptr;
    if (active) {
        if (s < MM) {                             // mems row s
            src = mems + (size_t)s * LL;
            dst = reinterpret_cast<float4*>(g_mems_enc) + (size_t)s * VD4;
        } else if (s == MM) {                     // xs -> mems_enc row M
            src = xs;
            dst = reinterpret_cast<float4*>(g_mems_enc) + (size_t)MM * VD4;
        } else if (s == MM + 1) {                 // ys -> ys_out row 0
            src = ys;
            dst = reinterpret_cast<float4*>(out_ys);
        } else {                                  // cand c -> ys_out row 1+c
            const int c = s - (MM + 2);
            src = cands + (size_t)c * LL;
            dst = reinterpret_cast<float4*>(out_ys) + (size_t)(1 + c) * VD4;
        }
    }

    // First warp of each group loads tokens + computes normalized weights
    if (active && j < LL) {
        int tok = src[j];
        toks[g][j] = tok;
        float w = freqs[tok];
        float sq = w * w;
        #pragma unroll
        for (int o = 16; o; o >>= 1) sq += __shfl_xor_sync(0xFFFFFFFFu, sq, o);
        ws[g][j] = w * rsqrtf(sq);
    }
    __syncthreads();

    if (active) {
        const float4* __restrict__ lt4 = reinterpret_cast<const float4*>(lt);
        float4 acc = make_float4(0.f, 0.f, 0.f, 0.f);
        #pragma unroll
        for (int l = 0; l < LL; l++) {
            const float w = ws[g][l];
            const float4 e = lt4[(size_t)toks[g][l] * VD4 + j];
            acc.x = fmaf(w, e.x, acc.x);
            acc.y = fmaf(w, e.y, acc.y);
            acc.z = fmaf(w, e.z, acc.z);
            acc.w = fmaf(w, e.w, acc.w);
        }
        __stcs(dst + j, acc);        // streaming store: keep lt resident
    }
}

// ---------------------------------------------------------------------------
// Kernel 2: cosine of every mems_enc row vs row M (xs). 4 rows per block,
// 64 threads per row, float4.
// ---------------------------------------------------------------------------
__global__ void cos_kernel()
{
    __shared__ float red[4][2][3];   // [group][warp-in-group][{dot, mn, xn}]

    const int t = threadIdx.x;
    const int g = t >> 6;
    const int j = t & 63;
    const int r = blockIdx.x * 4 + g;
    if (r >= ROWS) return;

    const float4* __restrict__ enc4 = reinterpret_cast<const float4*>(g_mems_enc);
    const float4 mv = __ldcs(enc4 + (size_t)r * VD4 + j);
    const float4 xv = enc4[(size_t)MM * VD4 + j];

    float dot = mv.x * xv.x + mv.y * xv.y + mv.z * xv.z + mv.w * xv.w;
    float mn  = mv.x * mv.x + mv.y * mv.y + mv.z * mv.z + mv.w * mv.w;
    float xn  = xv.x * xv.x + xv.y * xv.y + xv.z * xv.z + xv.w * xv.w;

    #pragma unroll
    for (int o = 16; o; o >>= 1) {
        dot += __shfl_xor_sync(0xFFFFFFFFu, dot, o);
        mn  += __shfl_xor_sync(0xFFFFFFFFu, mn, o);
        xn  += __shfl_xor_sync(0xFFFFFFFFu, xn, o);
    }
    const int wig = j >> 5;
    if ((j & 31) == 0) {
        red[g][wig][0] = dot; red[g][wig][1] = mn; red[g][wig][2] = xn;
    }
    __syncthreads();

    if (j == 0) {
        float d  = red[g][0][0] + red[g][1][0];
        float m  = red[g][0][1] + red[g][1][1];
        float x2 = red[g][0][2] + red[g][1][2];
        float an = fmaxf(sqrtf(x2), EPS);
        float bn = fmaxf(sqrtf(m),  EPS);
        g_cos[r] = d / (an * bn);
    }
}

// ---------------------------------------------------------------------------
// Kernel 3: fused softmax + partial att @ mems_enc.
// 256 blocks x 256 threads. Each block recomputes softmax stats from g_cos
// (16KB, L2-hot), then its partial weighted row sum. Deterministic.
// Block 0 / group 0 also folds row 4096 (xs).
// Partial rows stored with PLAIN stores (small, re-read next kernel: keep L2).
// ---------------------------------------------------------------------------
__global__ void lhs_partial_kernel()
{
    __shared__ float  sred[8];
    __shared__ float4 scomb[4][VD4];

    const int t = threadIdx.x;
    const int lane = t & 31;
    const int wid  = t >> 5;

    // --- softmax stats over g_cos ---
    float m = -INFINITY;
    for (int r = t; r < ROWS; r += 256) m = fmaxf(m, g_cos[r]);
    #pragma unroll
    for (int o = 16; o; o >>= 1) m = fmaxf(m, __shfl_xor_sync(0xFFFFFFFFu, m, o));
    if (lane == 0) sred[wid] = m;
    __syncthreads();
    {
        float mm = (t < 8) ? sred[t] : -INFINITY;
        if (wid == 0) {
            #pragma unroll
            for (int o = 4; o; o >>= 1) mm = fmaxf(mm, __shfl_xor_sync(0xFFFFFFFFu, mm, o));
            if (lane == 0) sred[0] = mm;
        }
    }
    __syncthreads();
    m = sred[0];
    __syncthreads();

    float s = 0.0f;
    for (int r = t; r < ROWS; r += 256) s += __expf(g_cos[r] - m);
    #pragma unroll
    for (int o = 16; o; o >>= 1) s += __shfl_xor_sync(0xFFFFFFFFu, s, o);
    if (lane == 0) sred[wid] = s;
    __syncthreads();
    {
        float ss = (t < 8) ? sred[t] : 0.0f;
        if (wid == 0) {
            #pragma unroll
            for (int o = 4; o; o >>= 1) ss += __shfl_xor_sync(0xFFFFFFFFu, ss, o);
            if (lane == 0) sred[0] = ss;
        }
    }
    __syncthreads();
    const float inv = 1.0f / sred[0];

    // --- partial weighted sum ---
    const int g = t >> 6;
    const int j = t & 63;
    const int base = (blockIdx.x * 4 + g) * 4;

    const float4* __restrict__ enc4 = reinterpret_cast<const float4*>(g_mems_enc);
    float4 acc = make_float4(0.f, 0.f, 0.f, 0.f);

    #pragma unroll
    for (int k = 0; k < 4; k++) {
        const int r = base + k;
        const float a = __expf(g_cos[r] - m) * inv;
        const float4 e = __ldcs(enc4 + (size_t)r * VD4 + j);
        acc.x = fmaf(a, e.x, acc.x);
        acc.y = fmaf(a, e.y, acc.y);
        acc.z = fmaf(a, e.z, acc.z);
        acc.w = fmaf(a, e.w, acc.w);
    }
    if (blockIdx.x == 0 && g == 0) {     // extra row 4096 (xs)
        const float a = __expf(g_cos[MM] - m) * inv;
        const float4 e = enc4[(size_t)MM * VD4 + j];
        acc.x = fmaf(a, e.x, acc.x);
        acc.y = fmaf(a, e.y, acc.y);
        acc.z = fmaf(a, e.z, acc.z);
        acc.w = fmaf(a, e.w, acc.w);
    }

    scomb[g][j] = acc;
    __syncthreads();

    if (g == 0) {
        float4 a0 = scomb[0][j], a1 = scomb[1][j], a2 = scomb[2][j], a3 = scomb[3][j];
        float4 r;
        r.x = (a0.x + a1.x) + (a2.x + a3.x);
        r.y = (a0.y + a1.y) + (a2.y + a3.y);
        r.z = (a0.z + a1.z) + (a2.z + a3.z);
        r.w = (a0.w + a1.w) + (a2.w + a3.w);
        reinterpret_cast<float4*>(g_partial)[(size_t)blockIdx.x * VD4 + j] = r;  // plain: keep L2
    }
}

// ---------------------------------------------------------------------------
// Kernel 4: reduce 256 partial rows -> g_lhs. 64 blocks (one per float4 col),
// 256 threads: thread t reads partial row t's float4 for this column (all 256
// loads in flight, L2-hit latency), then 4-component block reduce.
// ---------------------------------------------------------------------------
__global__ void lhs_final_kernel()
{
    __shared__ float4 sred4[8];

    const int j = blockIdx.x;        // float4 column 0..63
    const int t = threadIdx.x;       // partial row 0..255
    const int lane = t & 31;
    const int wid  = t >> 5;

    const float4* __restrict__ p4 = reinterpret_cast<const float4*>(g_partial);
    float4 v = p4[(size_t)t * VD4 + j];

    #pragma unroll
    for (int o = 16; o; o >>= 1) {
        v.x += __shfl_xor_sync(0xFFFFFFFFu, v.x, o);
        v.y += __shfl_xor_sync(0xFFFFFFFFu, v.y, o);
        v.z += __shfl_xor_sync(0xFFFFFFFFu, v.z, o);
        v.w += __shfl_xor_sync(0xFFFFFFFFu, v.w, o);
    }
    if (lane == 0) sred4[wid] = v;
    __syncthreads();

    if (t < 32) {
        float4 r = (lane < 8) ? sred4[lane] : make_float4(0.f, 0.f, 0.f, 0.f);
        #pragma unroll
        for (int o = 4; o; o >>= 1) {
            r.x += __shfl_xor_sync(0xFFFFFFFFu, r.x, o);
            r.y += __shfl_xor_sync(0xFFFFFFFFu, r.y, o);
            r.z += __shfl_xor_sync(0xFFFFFFFFu, r.z, o);
            r.w += __shfl_xor_sync(0xFFFFFFFFu, r.w, o);
        }
        if (lane == 0) reinterpret_cast<float4*>(g_lhs)[j] = r;
    }
}

// ---------------------------------------------------------------------------
// Kernel 5: tile g_lhs into xs_out (C+1 identical rows). float4, 4 rows/block,
// streaming stores.
// ---------------------------------------------------------------------------
__global__ void tile_kernel(float* __restrict__ out_xs)
{
    const int t = threadIdx.x;
    const int row = blockIdx.x * 4 + (t >> 6);
    const int j = t & 63;
    if (row <= CC) {
        const float4 v = reinterpret_cast<const float4*>(g_lhs)[j];
        __stcs(reinterpret_cast<float4*>(out_xs) + (size_t)row * VD4 + j, v);
    }
}

// ---------------------------------------------------------------------------
extern "C" void kernel_launch(void* const* d_in, const int* in_sizes, int n_in,
                              void* d_out, int out_size)
{
    const int*   xs    = (const int*)  d_in[0];
    const int*   mems  = (const int*)  d_in[1];
    const int*   ys    = (const int*)  d_in[2];
    const int*   cands = (const int*)  d_in[3];
    const float* lt    = (const float*)d_in[4];
    const float* freqs = (const float*)d_in[5];

    float* out    = (float*)d_out;
    float* out_xs = out;                          // [C+1, D]
    float* out_ys = out + (size_t)(CC + 1) * VD;  // [C+1, D]

    encode_kernel<<<(NSEQ + 3) / 4, VD>>>(xs, mems, ys, cands, lt, freqs, out_ys);
    cos_kernel<<<(ROWS + 3) / 4, VD>>>();
    lhs_partial_kernel<<<NLHS, VD>>>();
    lhs_final_kernel<<<VD4, VD>>>();
    tile_kernel<<<(CC + 1 + 3) / 4, VD>>>(out_xs);
}